// round 14
// baseline (speedup 1.0000x reference)
#include <cuda_runtime.h>
#include <cuda_bf16.h>
#include <cstdint>
#include <math.h>

#define N_NODES 50000
#define FEAT    512
#define HH      64      // HEADS*HID
#define HEADS   8
#define NCLS    7
#define BUCKET  96      // per-node src capacity; P(deg>96) ~ 1e-18 (Poisson(32)+1)

typedef unsigned long long u64;
typedef unsigned int u32;

// ---------------- scratch (device globals: no allocations allowed) ----------
__device__ float g_xl1[N_NODES * HH];
__device__ float g_xr1[N_NODES * HH];
__device__ float g_xl2[N_NODES * 8];
__device__ float g_xr2[N_NODES * 8];
__device__ int   g_idx64;
// bf16 hi/lo images of B = [Wl | Wr], layout [n][k]
__device__ __nv_bfloat16 g_Bh[128 * FEAT];
__device__ __nv_bfloat16 g_Bl[128 * FEAT];
// bucketed adjacency: deg counter + fixed-stride src lists
__device__ int g_deg[N_NODES];
__device__ int g_srcs[N_NODES * BUCKET];   // 19.2 MB

// ---------------- generic helpers -------------------------------------------
__device__ __forceinline__ float lrelu(float v) { return fmaxf(v, 0.2f * v); }

__device__ __forceinline__ void load_edge(const void* ei, int E, int eid,
                                          int idx64, int& s, int& d) {
    if (eid < E) {
        if (idx64) {
            s = (int)((const long long*)ei)[eid];
            d = (int)((const long long*)ei)[E + eid];
        } else {
            s = ((const int*)ei)[eid];
            d = ((const int*)ei)[E + eid];
        }
    } else {
        s = d = eid - E;
    }
}

__device__ __forceinline__ u32 smem_u32(const void* p) {
    u32 a;
    asm("{ .reg .u64 t; cvta.to.shared.u64 t, %1; cvt.u32.u64 %0, t; }" : "=r"(a) : "l"(p));
    return a;
}

__device__ __forceinline__ void ldsm_x4(u32 addr, u32& r0, u32& r1, u32& r2, u32& r3) {
    asm volatile("ldmatrix.sync.aligned.m8n8.x4.shared.b16 {%0,%1,%2,%3}, [%4];"
                 : "=r"(r0), "=r"(r1), "=r"(r2), "=r"(r3) : "r"(addr));
}

__device__ __forceinline__ void mma_bf16(float* c, const u32* a, const u32* b) {
    asm volatile("mma.sync.aligned.m16n8k16.row.col.f32.bf16.bf16.f32 "
                 "{%0,%1,%2,%3}, {%4,%5,%6,%7}, {%8,%9}, {%0,%1,%2,%3};"
                 : "+f"(c[0]), "+f"(c[1]), "+f"(c[2]), "+f"(c[3])
                 : "r"(a[0]), "r"(a[1]), "r"(a[2]), "r"(a[3]), "r"(b[0]), "r"(b[1]));
}

// ---------------- K_probe: dtype probe (1 thread) ----------------------------
__global__ void probe_kernel(const int* __restrict__ ei_words) {
    int all_zero = 1;
    #pragma unroll
    for (int j = 0; j < 64; j++)
        if (ei_words[2 * j + 1] != 0) { all_zero = 0; break; }
    g_idx64 = all_zero;
}

// ---------------- K_prepB: bf16 hi/lo images of [Wl|Wr] ----------------------
__global__ void prepB_kernel(const float* __restrict__ Wl, const float* __restrict__ Wr) {
    int i = blockIdx.x * blockDim.x + threadIdx.x;
    if (i >= 128 * FEAT) return;
    int n = i >> 9;
    int k = i & 511;
    float w = (n < HH) ? Wl[k * HH + n] : Wr[k * HH + (n - HH)];
    __nv_bfloat16 hi = __float2bfloat16(w);
    __nv_bfloat16 lo = __float2bfloat16(w - __bfloat162float(hi));
    g_Bh[i] = hi;
    g_Bl[i] = lo;
}

// ---------------- bucket scatter: one pass, no hist/scan ---------------------
__global__ void scatter_kernel(const void* __restrict__ ei, int E) {
    int eid = blockIdx.x * blockDim.x + threadIdx.x;
    int E2 = E + N_NODES;
    if (eid >= E2) return;
    int s, d;
    load_edge(ei, E, eid, g_idx64, s, d);
    if ((unsigned)s >= N_NODES || (unsigned)d >= N_NODES) return;
    int p = atomicAdd(&g_deg[d], 1);
    if (p < BUCKET) g_srcs[d * BUCKET + p] = s;
}

// ---------------- K1: proj1 via mma.sync bf16x3 ------------------------------
#define ASTR 72
#define BSTR 72
#define S_AH 0
#define S_AL 9216
#define S_BH 18432
#define S_BL 36864
#define S_BIAS 55296
#define PROJ_SMEM (55296 + 512)

__global__ __launch_bounds__(128) void proj1_kernel(
    const float* __restrict__ x,
    const float* __restrict__ bl, const float* __restrict__ br)
{
    extern __shared__ __align__(16) char smem[];
    const u32 sb = smem_u32(smem);
    const int tid  = threadIdx.x;
    const int lane = tid & 31;
    const int w    = tid >> 5;
    const int m0   = blockIdx.x * 64;

    ((float*)(smem + S_BIAS))[tid] = (tid < HH) ? bl[tid] : br[tid - HH];

    float acc[2][8][4];
    #pragma unroll
    for (int m = 0; m < 2; m++)
        #pragma unroll
        for (int t = 0; t < 8; t++)
            #pragma unroll
            for (int j = 0; j < 4; j++) acc[m][t][j] = 0.f;

    const int wr0 = (w & 1) * 32;
    const int nc0 = (w >> 1) * 64;
    const int r   = lane & 7;
    const int bq  = lane >> 3;
    const u32 offA = (u32)(((wr0 + (bq & 1) * 8 + r) * ASTR + (bq >> 1) * 8) * 2);
    const u32 offB = (u32)(((nc0 + (bq >> 1) * 8 + r) * BSTR + (bq & 1) * 8) * 2);

    for (int c = 0; c < 8; c++) {
        #pragma unroll
        for (int i = 0; i < 8; i++) {
            int idx = tid + i * 128;
            int row = idx >> 4;
            int kq  = (idx & 15) * 4;
            float4 v = make_float4(0.f, 0.f, 0.f, 0.f);
            if (m0 + row < N_NODES)
                v = *reinterpret_cast<const float4*>(x + (size_t)(m0 + row) * FEAT + c * 64 + kq);
            __nv_bfloat162 h01 = __floats2bfloat162_rn(v.x, v.y);
            __nv_bfloat162 h23 = __floats2bfloat162_rn(v.z, v.w);
            __nv_bfloat162 l01 = __floats2bfloat162_rn(v.x - __bfloat162float(h01.x),
                                                       v.y - __bfloat162float(h01.y));
            __nv_bfloat162 l23 = __floats2bfloat162_rn(v.z - __bfloat162float(h23.x),
                                                       v.w - __bfloat162float(h23.y));
            u32 off = (u32)((row * ASTR + kq) * 2);
            *reinterpret_cast<__nv_bfloat162*>(smem + S_AH + off)     = h01;
            *reinterpret_cast<__nv_bfloat162*>(smem + S_AH + off + 4) = h23;
            *reinterpret_cast<__nv_bfloat162*>(smem + S_AL + off)     = l01;
            *reinterpret_cast<__nv_bfloat162*>(smem + S_AL + off + 4) = l23;
        }
        #pragma unroll
        for (int i = 0; i < 8; i++) {
            int idx = tid + i * 128;
            int n   = idx >> 3;
            int kq  = (idx & 7) * 8;
            uint4 vh = *reinterpret_cast<const uint4*>(g_Bh + (size_t)n * FEAT + c * 64 + kq);
            uint4 vl = *reinterpret_cast<const uint4*>(g_Bl + (size_t)n * FEAT + c * 64 + kq);
            u32 off = (u32)((n * BSTR + kq) * 2);
            *reinterpret_cast<uint4*>(smem + S_BH + off) = vh;
            *reinterpret_cast<uint4*>(smem + S_BL + off) = vl;
        }
        __syncthreads();

        #pragma unroll
        for (int s = 0; s < 4; s++) {
            u32 ah[2][4], al[2][4], bh[8][2], blo[8][2];
            #pragma unroll
            for (int m = 0; m < 2; m++) {
                u32 ao = offA + (u32)((m * 16 * ASTR + s * 16) * 2);
                ldsm_x4(sb + S_AH + ao, ah[m][0], ah[m][1], ah[m][2], ah[m][3]);
                ldsm_x4(sb + S_AL + ao, al[m][0], al[m][1], al[m][2], al[m][3]);
            }
            #pragma unroll
            for (int t = 0; t < 8; t += 2) {
                u32 bo = offB + (u32)((t * 8 * BSTR + s * 16) * 2);
                ldsm_x4(sb + S_BH + bo, bh[t][0], bh[t][1], bh[t + 1][0], bh[t + 1][1]);
                ldsm_x4(sb + S_BL + bo, blo[t][0], blo[t][1], blo[t + 1][0], blo[t + 1][1]);
            }
            #pragma unroll
            for (int m = 0; m < 2; m++)
                #pragma unroll
                for (int t = 0; t < 8; t++) {
                    mma_bf16(acc[m][t], ah[m], bh[t]);
                    mma_bf16(acc[m][t], ah[m], blo[t]);
                    mma_bf16(acc[m][t], al[m], bh[t]);
                }
        }
        __syncthreads();
    }

    const float* sbias = (const float*)(smem + S_BIAS);
    #pragma unroll
    for (int m = 0; m < 2; m++) {
        int row = m0 + wr0 + m * 16 + (lane >> 2);
        #pragma unroll
        for (int t = 0; t < 8; t++) {
            int col = nc0 + t * 8 + 2 * (lane & 3);
            float b0 = sbias[col], b1 = sbias[col + 1];
            float* basep = (col < HH) ? g_xl1 : g_xr1;
            int    cc    = (col < HH) ? col : col - HH;
            if (row < N_NODES) {
                float2 v = make_float2(acc[m][t][0] + b0, acc[m][t][1] + b1);
                *reinterpret_cast<float2*>(basep + (size_t)row * HH + cc) = v;
            }
            if (row + 8 < N_NODES) {
                float2 v = make_float2(acc[m][t][2] + b0, acc[m][t][3] + b1);
                *reinterpret_cast<float2*>(basep + (size_t)(row + 8) * HH + cc) = v;
            }
        }
    }
}

// ---------------- K2: layer-1 aggregation + finalize + proj2 (fused) ---------
// TWO warps per node (per-head independence): warp = (node, head-group of 4).
// lane = (j, h4): j = lane>>2 (8 edge slots), h = hg*4 + (lane&3).
// No cross-warp reduction needed for aggregation; epilogue syncs the block.
__global__ __launch_bounds__(256) void agg1_kernel(
    const float* __restrict__ att, const float* __restrict__ bias1,
    const float* __restrict__ Wl2, const float* __restrict__ bl2,
    const float* __restrict__ Wr2, const float* __restrict__ br2)
{
    __shared__ float sW[HH * 14];
    __shared__ float sbv[14];
    __shared__ float sh[4][HH];
    const int tid   = threadIdx.x;
    const int warp  = tid >> 5;
    const int lane  = tid & 31;
    const int nwarp = warp >> 1;        // node slot in block (0..3)
    const int hg    = warp & 1;         // head group (0..1)
    const int h     = hg * 4 + (lane & 3);
    const int j     = lane >> 2;        // edge slot (0..7)

    for (int i = tid; i < HH * 14; i += 256) {
        int k = i / 14, jj = i - k * 14;
        sW[i] = (jj < NCLS) ? Wl2[k * NCLS + jj] : Wr2[k * NCLS + (jj - NCLS)];
    }
    if (tid < 14) sbv[tid] = (tid < NCLS) ? bl2[tid] : br2[tid - NCLS];
    __syncthreads();

    const int n = blockIdx.x * 4 + nwarp;   // grid = 12500, exact

    const float4* at = reinterpret_cast<const float4*>(att + h * 8);
    const float4 t0 = at[0], t1 = at[1];

    const float4* xb = reinterpret_cast<const float4*>(g_xr1 + (size_t)n * HH + h * 8);
    const float4 b0 = xb[0], b1 = xb[1];

    const int deg = min(g_deg[n], BUCKET);
    const int* srcp = g_srcs + (size_t)n * BUCKET;

    float4 A0 = make_float4(0.f, 0.f, 0.f, 0.f);
    float4 A1 = make_float4(0.f, 0.f, 0.f, 0.f);
    float den = 0.f;

    for (int i = j; i < deg; i += 8) {
        int src = __ldg(srcp + i);
        const float4* xa = reinterpret_cast<const float4*>(g_xl1 + (size_t)src * HH + h * 8);
        float4 a0 = xa[0], a1 = xa[1];

        float e = lrelu(a0.x + b0.x) * t0.x + lrelu(a0.y + b0.y) * t0.y
                + lrelu(a0.z + b0.z) * t0.z + lrelu(a0.w + b0.w) * t0.w
                + lrelu(a1.x + b1.x) * t1.x + lrelu(a1.y + b1.y) * t1.y
                + lrelu(a1.z + b1.z) * t1.z + lrelu(a1.w + b1.w) * t1.w;
        float w = expf(e);

        A0.x += w * a0.x; A0.y += w * a0.y; A0.z += w * a0.z; A0.w += w * a0.w;
        A1.x += w * a1.x; A1.y += w * a1.y; A1.z += w * a1.z; A1.w += w * a1.w;
        den += w;
    }

    // reduce over the 8 edge slots (j lives in lane bits 2..4 -> xor 4, 8, 16)
    #pragma unroll
    for (int m = 4; m <= 16; m <<= 1) {
        A0.x += __shfl_xor_sync(0xFFFFFFFF, A0.x, m);
        A0.y += __shfl_xor_sync(0xFFFFFFFF, A0.y, m);
        A0.z += __shfl_xor_sync(0xFFFFFFFF, A0.z, m);
        A0.w += __shfl_xor_sync(0xFFFFFFFF, A0.w, m);
        A1.x += __shfl_xor_sync(0xFFFFFFFF, A1.x, m);
        A1.y += __shfl_xor_sync(0xFFFFFFFF, A1.y, m);
        A1.z += __shfl_xor_sync(0xFFFFFFFF, A1.z, m);
        A1.w += __shfl_xor_sync(0xFFFFFFFF, A1.w, m);
        den  += __shfl_xor_sync(0xFFFFFFFF, den,  m);
    }

    if (j == 0) {   // lanes 0..3 of each warp: head h
        float inv = 1.f / den;
        float o[8];
        o[0] = A0.x * inv + bias1[h * 8 + 0];
        o[1] = A0.y * inv + bias1[h * 8 + 1];
        o[2] = A0.z * inv + bias1[h * 8 + 2];
        o[3] = A0.w * inv + bias1[h * 8 + 3];
        o[4] = A1.x * inv + bias1[h * 8 + 4];
        o[5] = A1.y * inv + bias1[h * 8 + 5];
        o[6] = A1.z * inv + bias1[h * 8 + 6];
        o[7] = A1.w * inv + bias1[h * 8 + 7];
        #pragma unroll
        for (int q = 0; q < 8; q++)
            sh[nwarp][h * 8 + q] = (o[q] > 0.f) ? o[q] : expm1f(o[q]);   // ELU
    }
    __syncthreads();   // both head-group warps of each node must finish

    if (tid < 56) {
        int nd = tid / 14, jj = tid - nd * 14;
        float acc = sbv[jj];
        const float* hrow = sh[nd];
        #pragma unroll
        for (int k = 0; k < HH; k++) acc += hrow[k] * sW[k * 14 + jj];
        int n2 = blockIdx.x * 4 + nd;
        if (jj < NCLS) g_xl2[(size_t)n2 * 8 + jj] = acc;
        else           g_xr2[(size_t)n2 * 8 + (jj - NCLS)] = acc;
    }
}

// ---------------- K3: layer-2 aggregation + log_softmax (fused) --------------
__global__ __launch_bounds__(256) void agg2_kernel(
    const float* __restrict__ att2, const float* __restrict__ bias2,
    float* __restrict__ out)
{
    const int n    = blockIdx.x * 8 + (threadIdx.x >> 5);
    const int lane = threadIdx.x & 31;
    if (n >= N_NODES) return;

    float a2[NCLS];
    #pragma unroll
    for (int c = 0; c < NCLS; c++) a2[c] = att2[c];

    const float4* xb = reinterpret_cast<const float4*>(g_xr2 + (size_t)n * 8);
    const float4 q0 = xb[0], q1 = xb[1];

    const int deg = min(g_deg[n], BUCKET);
    const int* srcp = g_srcs + (size_t)n * BUCKET;

    float4 P0 = make_float4(0.f, 0.f, 0.f, 0.f);
    float4 P1 = make_float4(0.f, 0.f, 0.f, 0.f);   // .w = denominator

    for (int i = lane; i < deg; i += 32) {
        int src = __ldg(srcp + i);
        const float4* xa = reinterpret_cast<const float4*>(g_xl2 + (size_t)src * 8);
        float4 p0 = xa[0], p1 = xa[1];

        float e = lrelu(p0.x + q0.x) * a2[0] + lrelu(p0.y + q0.y) * a2[1]
                + lrelu(p0.z + q0.z) * a2[2] + lrelu(p0.w + q0.w) * a2[3]
                + lrelu(p1.x + q1.x) * a2[4] + lrelu(p1.y + q1.y) * a2[5]
                + lrelu(p1.z + q1.z) * a2[6];
        float w = expf(e);

        P0.x += w * p0.x; P0.y += w * p0.y; P0.z += w * p0.z; P0.w += w * p0.w;
        P1.x += w * p1.x; P1.y += w * p1.y; P1.z += w * p1.z; P1.w += w;
    }

    #pragma unroll
    for (int m = 1; m <= 16; m <<= 1) {
        P0.x += __shfl_xor_sync(0xFFFFFFFF, P0.x, m);
        P0.y += __shfl_xor_sync(0xFFFFFFFF, P0.y, m);
        P0.z += __shfl_xor_sync(0xFFFFFFFF, P0.z, m);
        P0.w += __shfl_xor_sync(0xFFFFFFFF, P0.w, m);
        P1.x += __shfl_xor_sync(0xFFFFFFFF, P1.x, m);
        P1.y += __shfl_xor_sync(0xFFFFFFFF, P1.y, m);
        P1.z += __shfl_xor_sync(0xFFFFFFFF, P1.z, m);
        P1.w += __shfl_xor_sync(0xFFFFFFFF, P1.w, m);
    }

    if (lane == 0) {
        float inv = 1.f / P1.w;
        float v[NCLS];
        v[0] = P0.x * inv + bias2[0];
        v[1] = P0.y * inv + bias2[1];
        v[2] = P0.z * inv + bias2[2];
        v[3] = P0.w * inv + bias2[3];
        v[4] = P1.x * inv + bias2[4];
        v[5] = P1.y * inv + bias2[5];
        v[6] = P1.z * inv + bias2[6];

        float m = v[0];
        #pragma unroll
        for (int c = 1; c < NCLS; c++) m = fmaxf(m, v[c]);
        float ssum = 0.f;
        #pragma unroll
        for (int c = 0; c < NCLS; c++) ssum += expf(v[c] - m);
        float l = m + logf(ssum);
        #pragma unroll
        for (int c = 0; c < NCLS; c++) out[(size_t)n * NCLS + c] = v[c] - l;
    }
}

// ---------------- launch -----------------------------------------------------
extern "C" void kernel_launch(void* const* d_in, const int* in_sizes, int n_in,
                              void* d_out, int out_size)
{
    const float* x     = (const float*)d_in[0];
    const void*  ei    = d_in[1];
    const float* Wl1   = (const float*)d_in[2];
    const float* bl1   = (const float*)d_in[3];
    const float* Wr1   = (const float*)d_in[4];
    const float* br1   = (const float*)d_in[5];
    const float* att1  = (const float*)d_in[6];
    const float* bias1 = (const float*)d_in[7];
    const float* Wl2   = (const float*)d_in[8];
    const float* bl2   = (const float*)d_in[9];
    const float* Wr2   = (const float*)d_in[10];
    const float* br2   = (const float*)d_in[11];
    const float* att2  = (const float*)d_in[12];
    const float* bias2 = (const float*)d_in[13];

    const int E  = in_sizes[1] / 2;          // 1,600,000
    const int E2 = E + N_NODES;

    // one-time resource setup (first call = eager correctness run, not capture)
    static cudaStream_t s_side = nullptr;
    static cudaEvent_t  ev_fork = nullptr, ev_join = nullptr;
    static void* deg_addr = nullptr;
    if (s_side == nullptr) {
        cudaStreamCreateWithFlags(&s_side, cudaStreamNonBlocking);
        cudaEventCreateWithFlags(&ev_fork, cudaEventDisableTiming);
        cudaEventCreateWithFlags(&ev_join, cudaEventDisableTiming);
        cudaGetSymbolAddress(&deg_addr, g_deg);
        cudaFuncSetAttribute(proj1_kernel,
                             cudaFuncAttributeMaxDynamicSharedMemorySize, PROJ_SMEM);
    }

    // fork: projection chain on side stream
    cudaEventRecord(ev_fork, 0);
    cudaStreamWaitEvent(s_side, ev_fork, 0);
    prepB_kernel<<<(128 * FEAT + 255) / 256, 256, 0, s_side>>>(Wl1, Wr1);
    proj1_kernel<<<(N_NODES + 63) / 64, 128, PROJ_SMEM, s_side>>>(x, bl1, br1);
    cudaEventRecord(ev_join, s_side);

    // adjacency chain on main (capture-origin) stream: one-pass bucket scatter
    cudaMemsetAsync(deg_addr, 0, N_NODES * sizeof(int), 0);
    probe_kernel<<<1, 1>>>((const int*)ei);
    scatter_kernel<<<(E2 + 255) / 256, 256>>>(ei, E);

    // join: aggregation needs both chains
    cudaStreamWaitEvent(0, ev_join, 0);
    agg1_kernel<<<N_NODES / 4, 256>>>(att1, bias1, Wl2, bl2, Wr2, br2);
    agg2_kernel<<<(N_NODES + 7) / 8, 256>>>(att2, bias2, (float*)d_out);
}

// round 17
// speedup vs baseline: 1.1339x; 1.1339x over previous
#include <cuda_runtime.h>
#include <cuda_bf16.h>
#include <cuda_fp16.h>
#include <cstdint>
#include <math.h>

#define N_NODES 50000
#define FEAT    512
#define HH      64      // HEADS*HID
#define HEADS   8
#define NCLS    7
#define BUCKET  96      // per-node src capacity; P(deg>96) ~ 1e-18 (Poisson(32)+1)

typedef unsigned long long u64;
typedef unsigned int u32;

// ---------------- scratch (device globals: no allocations allowed) ----------
__device__ __half g_xl1h[N_NODES * HH];   // fp16 gather operand (6.4 MB)
__device__ float  g_xr1[N_NODES * HH];
__device__ float  g_xl2[N_NODES * 8];
__device__ float  g_xr2[N_NODES * 8];
__device__ int    g_idx64;
// bf16 hi/lo images of B = [Wl | Wr], layout [n][k]
__device__ __nv_bfloat16 g_Bh[128 * FEAT];
__device__ __nv_bfloat16 g_Bl[128 * FEAT];
// bucketed adjacency: deg counter + fixed-stride src lists
__device__ int g_deg[N_NODES];
__device__ int g_srcs[N_NODES * BUCKET];   // 19.2 MB

// ---------------- generic helpers -------------------------------------------
__device__ __forceinline__ float lrelu(float v) { return fmaxf(v, 0.2f * v); }

__device__ __forceinline__ void load_edge(const void* ei, int E, int eid,
                                          int idx64, int& s, int& d) {
    if (eid < E) {
        if (idx64) {
            s = (int)((const long long*)ei)[eid];
            d = (int)((const long long*)ei)[E + eid];
        } else {
            s = ((const int*)ei)[eid];
            d = ((const int*)ei)[E + eid];
        }
    } else {
        s = d = eid - E;
    }
}

__device__ __forceinline__ u32 smem_u32(const void* p) {
    u32 a;
    asm("{ .reg .u64 t; cvta.to.shared.u64 t, %1; cvt.u32.u64 %0, t; }" : "=r"(a) : "l"(p));
    return a;
}

__device__ __forceinline__ void ldsm_x4(u32 addr, u32& r0, u32& r1, u32& r2, u32& r3) {
    asm volatile("ldmatrix.sync.aligned.m8n8.x4.shared.b16 {%0,%1,%2,%3}, [%4];"
                 : "=r"(r0), "=r"(r1), "=r"(r2), "=r"(r3) : "r"(addr));
}

__device__ __forceinline__ void mma_bf16(float* c, const u32* a, const u32* b) {
    asm volatile("mma.sync.aligned.m16n8k16.row.col.f32.bf16.bf16.f32 "
                 "{%0,%1,%2,%3}, {%4,%5,%6,%7}, {%8,%9}, {%0,%1,%2,%3};"
                 : "+f"(c[0]), "+f"(c[1]), "+f"(c[2]), "+f"(c[3])
                 : "r"(a[0]), "r"(a[1]), "r"(a[2]), "r"(a[3]), "r"(b[0]), "r"(b[1]));
}

// ---------------- K_probe: dtype probe (1 thread) ----------------------------
__global__ void probe_kernel(const int* __restrict__ ei_words) {
    int all_zero = 1;
    #pragma unroll
    for (int j = 0; j < 64; j++)
        if (ei_words[2 * j + 1] != 0) { all_zero = 0; break; }
    g_idx64 = all_zero;
}

// ---------------- K_prepB: bf16 hi/lo images of [Wl|Wr] ----------------------
__global__ void prepB_kernel(const float* __restrict__ Wl, const float* __restrict__ Wr) {
    int i = blockIdx.x * blockDim.x + threadIdx.x;
    if (i >= 128 * FEAT) return;
    int n = i >> 9;
    int k = i & 511;
    float w = (n < HH) ? Wl[k * HH + n] : Wr[k * HH + (n - HH)];
    __nv_bfloat16 hi = __float2bfloat16(w);
    __nv_bfloat16 lo = __float2bfloat16(w - __bfloat162float(hi));
    g_Bh[i] = hi;
    g_Bl[i] = lo;
}

// ---------------- bucket scatter: one pass, no hist/scan ---------------------
__global__ void scatter_kernel(const void* __restrict__ ei, int E) {
    int eid = blockIdx.x * blockDim.x + threadIdx.x;
    int E2 = E + N_NODES;
    if (eid >= E2) return;
    int s, d;
    load_edge(ei, E, eid, g_idx64, s, d);
    if ((unsigned)s >= N_NODES || (unsigned)d >= N_NODES) return;
    int p = atomicAdd(&g_deg[d], 1);
    if (p < BUCKET) g_srcs[d * BUCKET + p] = s;
}

// ---------------- K1: proj1 via mma.sync bf16x3 ------------------------------
#define ASTR 72
#define BSTR 72
#define S_AH 0
#define S_AL 9216
#define S_BH 18432
#define S_BL 36864
#define S_BIAS 55296
#define PROJ_SMEM (55296 + 512)

__global__ __launch_bounds__(128) void proj1_kernel(
    const float* __restrict__ x,
    const float* __restrict__ bl, const float* __restrict__ br)
{
    extern __shared__ __align__(16) char smem[];
    const u32 sb = smem_u32(smem);
    const int tid  = threadIdx.x;
    const int lane = tid & 31;
    const int w    = tid >> 5;
    const int m0   = blockIdx.x * 64;

    ((float*)(smem + S_BIAS))[tid] = (tid < HH) ? bl[tid] : br[tid - HH];

    float acc[2][8][4];
    #pragma unroll
    for (int m = 0; m < 2; m++)
        #pragma unroll
        for (int t = 0; t < 8; t++)
            #pragma unroll
            for (int j = 0; j < 4; j++) acc[m][t][j] = 0.f;

    const int wr0 = (w & 1) * 32;
    const int nc0 = (w >> 1) * 64;
    const int r   = lane & 7;
    const int bq  = lane >> 3;
    const u32 offA = (u32)(((wr0 + (bq & 1) * 8 + r) * ASTR + (bq >> 1) * 8) * 2);
    const u32 offB = (u32)(((nc0 + (bq >> 1) * 8 + r) * BSTR + (bq & 1) * 8) * 2);

    for (int c = 0; c < 8; c++) {
        #pragma unroll
        for (int i = 0; i < 8; i++) {
            int idx = tid + i * 128;
            int row = idx >> 4;
            int kq  = (idx & 15) * 4;
            float4 v = make_float4(0.f, 0.f, 0.f, 0.f);
            if (m0 + row < N_NODES)
                v = *reinterpret_cast<const float4*>(x + (size_t)(m0 + row) * FEAT + c * 64 + kq);
            __nv_bfloat162 h01 = __floats2bfloat162_rn(v.x, v.y);
            __nv_bfloat162 h23 = __floats2bfloat162_rn(v.z, v.w);
            __nv_bfloat162 l01 = __floats2bfloat162_rn(v.x - __bfloat162float(h01.x),
                                                       v.y - __bfloat162float(h01.y));
            __nv_bfloat162 l23 = __floats2bfloat162_rn(v.z - __bfloat162float(h23.x),
                                                       v.w - __bfloat162float(h23.y));
            u32 off = (u32)((row * ASTR + kq) * 2);
            *reinterpret_cast<__nv_bfloat162*>(smem + S_AH + off)     = h01;
            *reinterpret_cast<__nv_bfloat162*>(smem + S_AH + off + 4) = h23;
            *reinterpret_cast<__nv_bfloat162*>(smem + S_AL + off)     = l01;
            *reinterpret_cast<__nv_bfloat162*>(smem + S_AL + off + 4) = l23;
        }
        #pragma unroll
        for (int i = 0; i < 8; i++) {
            int idx = tid + i * 128;
            int n   = idx >> 3;
            int kq  = (idx & 7) * 8;
            uint4 vh = *reinterpret_cast<const uint4*>(g_Bh + (size_t)n * FEAT + c * 64 + kq);
            uint4 vl = *reinterpret_cast<const uint4*>(g_Bl + (size_t)n * FEAT + c * 64 + kq);
            u32 off = (u32)((n * BSTR + kq) * 2);
            *reinterpret_cast<uint4*>(smem + S_BH + off) = vh;
            *reinterpret_cast<uint4*>(smem + S_BL + off) = vl;
        }
        __syncthreads();

        #pragma unroll
        for (int s = 0; s < 4; s++) {
            u32 ah[2][4], al[2][4], bh[8][2], blo[8][2];
            #pragma unroll
            for (int m = 0; m < 2; m++) {
                u32 ao = offA + (u32)((m * 16 * ASTR + s * 16) * 2);
                ldsm_x4(sb + S_AH + ao, ah[m][0], ah[m][1], ah[m][2], ah[m][3]);
                ldsm_x4(sb + S_AL + ao, al[m][0], al[m][1], al[m][2], al[m][3]);
            }
            #pragma unroll
            for (int t = 0; t < 8; t += 2) {
                u32 bo = offB + (u32)((t * 8 * BSTR + s * 16) * 2);
                ldsm_x4(sb + S_BH + bo, bh[t][0], bh[t][1], bh[t + 1][0], bh[t + 1][1]);
                ldsm_x4(sb + S_BL + bo, blo[t][0], blo[t][1], blo[t + 1][0], blo[t + 1][1]);
            }
            #pragma unroll
            for (int m = 0; m < 2; m++)
                #pragma unroll
                for (int t = 0; t < 8; t++) {
                    mma_bf16(acc[m][t], ah[m], bh[t]);
                    mma_bf16(acc[m][t], ah[m], blo[t]);
                    mma_bf16(acc[m][t], al[m], bh[t]);
                }
        }
        __syncthreads();
    }

    // epilogue: xl cols (<64) -> fp16 half2 store; xr cols -> fp32 float2 store
    const float* sbias = (const float*)(smem + S_BIAS);
    #pragma unroll
    for (int m = 0; m < 2; m++) {
        int row = m0 + wr0 + m * 16 + (lane >> 2);
        #pragma unroll
        for (int t = 0; t < 8; t++) {
            int col = nc0 + t * 8 + 2 * (lane & 3);
            float b0 = sbias[col], b1 = sbias[col + 1];
            if (col < HH) {
                if (row < N_NODES) {
                    __half2 v = __floats2half2_rn(acc[m][t][0] + b0, acc[m][t][1] + b1);
                    *reinterpret_cast<__half2*>(g_xl1h + (size_t)row * HH + col) = v;
                }
                if (row + 8 < N_NODES) {
                    __half2 v = __floats2half2_rn(acc[m][t][2] + b0, acc[m][t][3] + b1);
                    *reinterpret_cast<__half2*>(g_xl1h + (size_t)(row + 8) * HH + col) = v;
                }
            } else {
                int cc = col - HH;
                if (row < N_NODES) {
                    float2 v = make_float2(acc[m][t][0] + b0, acc[m][t][1] + b1);
                    *reinterpret_cast<float2*>(g_xr1 + (size_t)row * HH + cc) = v;
                }
                if (row + 8 < N_NODES) {
                    float2 v = make_float2(acc[m][t][2] + b0, acc[m][t][3] + b1);
                    *reinterpret_cast<float2*>(g_xr1 + (size_t)(row + 8) * HH + cc) = v;
                }
            }
        }
    }
}

// ---------------- K2: layer-1 aggregation + finalize + proj2 (fused) ---------
// One warp per node; fp16 gather: one 16B load per lane per edge (one 128B
// line per warp per edge).
__global__ __launch_bounds__(256) void agg1_kernel(
    const float* __restrict__ att, const float* __restrict__ bias1,
    const float* __restrict__ Wl2, const float* __restrict__ bl2,
    const float* __restrict__ Wr2, const float* __restrict__ br2)
{
    __shared__ float sW[HH * 14];
    __shared__ float sbv[14];
    __shared__ float sh[8][HH];
    const int tid  = threadIdx.x;
    const int warp = tid >> 5;
    const int lane = tid & 31;
    const int h    = lane & 7;
    const int j    = lane >> 3;

    for (int i = tid; i < HH * 14; i += 256) {
        int k = i / 14, jj = i - k * 14;
        sW[i] = (jj < NCLS) ? Wl2[k * NCLS + jj] : Wr2[k * NCLS + (jj - NCLS)];
    }
    if (tid < 14) sbv[tid] = (tid < NCLS) ? bl2[tid] : br2[tid - NCLS];
    __syncthreads();

    const int n = blockIdx.x * 8 + warp;
    if (n >= N_NODES) return;

    const float4* at = reinterpret_cast<const float4*>(att + h * 8);
    const float4 t0 = at[0], t1 = at[1];

    const float4* xb = reinterpret_cast<const float4*>(g_xr1 + (size_t)n * HH + h * 8);
    const float4 b0 = xb[0], b1 = xb[1];

    const int deg = min(g_deg[n], BUCKET);
    const int* srcp = g_srcs + (size_t)n * BUCKET;

    float4 A0 = make_float4(0.f, 0.f, 0.f, 0.f);
    float4 A1 = make_float4(0.f, 0.f, 0.f, 0.f);
    float den = 0.f;

    for (int i = j; i < deg; i += 4) {
        int src = __ldg(srcp + i);
        uint4 raw = *reinterpret_cast<const uint4*>(g_xl1h + (size_t)src * HH + h * 8);
        float2 f0 = __half22float2(*reinterpret_cast<__half2*>(&raw.x));
        float2 f1 = __half22float2(*reinterpret_cast<__half2*>(&raw.y));
        float2 f2 = __half22float2(*reinterpret_cast<__half2*>(&raw.z));
        float2 f3 = __half22float2(*reinterpret_cast<__half2*>(&raw.w));
        float4 a0 = make_float4(f0.x, f0.y, f1.x, f1.y);
        float4 a1 = make_float4(f2.x, f2.y, f3.x, f3.y);

        float e = lrelu(a0.x + b0.x) * t0.x + lrelu(a0.y + b0.y) * t0.y
                + lrelu(a0.z + b0.z) * t0.z + lrelu(a0.w + b0.w) * t0.w
                + lrelu(a1.x + b1.x) * t1.x + lrelu(a1.y + b1.y) * t1.y
                + lrelu(a1.z + b1.z) * t1.z + lrelu(a1.w + b1.w) * t1.w;
        float w = expf(e);

        A0.x += w * a0.x; A0.y += w * a0.y; A0.z += w * a0.z; A0.w += w * a0.w;
        A1.x += w * a1.x; A1.y += w * a1.y; A1.z += w * a1.z; A1.w += w * a1.w;
        den += w;
    }

    #pragma unroll
    for (int m = 8; m <= 16; m <<= 1) {
        A0.x += __shfl_xor_sync(0xFFFFFFFF, A0.x, m);
        A0.y += __shfl_xor_sync(0xFFFFFFFF, A0.y, m);
        A0.z += __shfl_xor_sync(0xFFFFFFFF, A0.z, m);
        A0.w += __shfl_xor_sync(0xFFFFFFFF, A0.w, m);
        A1.x += __shfl_xor_sync(0xFFFFFFFF, A1.x, m);
        A1.y += __shfl_xor_sync(0xFFFFFFFF, A1.y, m);
        A1.z += __shfl_xor_sync(0xFFFFFFFF, A1.z, m);
        A1.w += __shfl_xor_sync(0xFFFFFFFF, A1.w, m);
        den  += __shfl_xor_sync(0xFFFFFFFF, den,  m);
    }

    if (j == 0) {   // lanes 0..7, h = lane
        float inv = 1.f / den;
        float o[8];
        o[0] = A0.x * inv + bias1[h * 8 + 0];
        o[1] = A0.y * inv + bias1[h * 8 + 1];
        o[2] = A0.z * inv + bias1[h * 8 + 2];
        o[3] = A0.w * inv + bias1[h * 8 + 3];
        o[4] = A1.x * inv + bias1[h * 8 + 4];
        o[5] = A1.y * inv + bias1[h * 8 + 5];
        o[6] = A1.z * inv + bias1[h * 8 + 6];
        o[7] = A1.w * inv + bias1[h * 8 + 7];
        #pragma unroll
        for (int q = 0; q < 8; q++)
            sh[warp][h * 8 + q] = (o[q] > 0.f) ? o[q] : expm1f(o[q]);   // ELU
    }
    __syncwarp();

    if (lane < 14) {
        float acc = sbv[lane];
        const float* hrow = sh[warp];
        #pragma unroll
        for (int k = 0; k < HH; k++) acc += hrow[k] * sW[k * 14 + lane];
        if (lane < NCLS) g_xl2[(size_t)n * 8 + lane] = acc;
        else             g_xr2[(size_t)n * 8 + (lane - NCLS)] = acc;
    }
}

// ---------------- K3: layer-2 aggregation + log_softmax (fused) --------------
__global__ __launch_bounds__(256) void agg2_kernel(
    const float* __restrict__ att2, const float* __restrict__ bias2,
    float* __restrict__ out)
{
    const int n    = blockIdx.x * 8 + (threadIdx.x >> 5);
    const int lane = threadIdx.x & 31;
    if (n >= N_NODES) return;

    float a2[NCLS];
    #pragma unroll
    for (int c = 0; c < NCLS; c++) a2[c] = att2[c];

    const float4* xb = reinterpret_cast<const float4*>(g_xr2 + (size_t)n * 8);
    const float4 q0 = xb[0], q1 = xb[1];

    const int deg = min(g_deg[n], BUCKET);
    const int* srcp = g_srcs + (size_t)n * BUCKET;

    float4 P0 = make_float4(0.f, 0.f, 0.f, 0.f);
    float4 P1 = make_float4(0.f, 0.f, 0.f, 0.f);   // .w = denominator

    for (int i = lane; i < deg; i += 32) {
        int src = __ldg(srcp + i);
        const float4* xa = reinterpret_cast<const float4*>(g_xl2 + (size_t)src * 8);
        float4 p0 = xa[0], p1 = xa[1];

        float e = lrelu(p0.x + q0.x) * a2[0] + lrelu(p0.y + q0.y) * a2[1]
                + lrelu(p0.z + q0.z) * a2[2] + lrelu(p0.w + q0.w) * a2[3]
                + lrelu(p1.x + q1.x) * a2[4] + lrelu(p1.y + q1.y) * a2[5]
                + lrelu(p1.z + q1.z) * a2[6];
        float w = expf(e);

        P0.x += w * p0.x; P0.y += w * p0.y; P0.z += w * p0.z; P0.w += w * p0.w;
        P1.x += w * p1.x; P1.y += w * p1.y; P1.z += w * p1.z; P1.w += w;
    }

    #pragma unroll
    for (int m = 1; m <= 16; m <<= 1) {
        P0.x += __shfl_xor_sync(0xFFFFFFFF, P0.x, m);
        P0.y += __shfl_xor_sync(0xFFFFFFFF, P0.y, m);
        P0.z += __shfl_xor_sync(0xFFFFFFFF, P0.z, m);
        P0.w += __shfl_xor_sync(0xFFFFFFFF, P0.w, m);
        P1.x += __shfl_xor_sync(0xFFFFFFFF, P1.x, m);
        P1.y += __shfl_xor_sync(0xFFFFFFFF, P1.y, m);
        P1.z += __shfl_xor_sync(0xFFFFFFFF, P1.z, m);
        P1.w += __shfl_xor_sync(0xFFFFFFFF, P1.w, m);
    }

    if (lane == 0) {
        float inv = 1.f / P1.w;
        float v[NCLS];
        v[0] = P0.x * inv + bias2[0];
        v[1] = P0.y * inv + bias2[1];
        v[2] = P0.z * inv + bias2[2];
        v[3] = P0.w * inv + bias2[3];
        v[4] = P1.x * inv + bias2[4];
        v[5] = P1.y * inv + bias2[5];
        v[6] = P1.z * inv + bias2[6];

        float m = v[0];
        #pragma unroll
        for (int c = 1; c < NCLS; c++) m = fmaxf(m, v[c]);
        float ssum = 0.f;
        #pragma unroll
        for (int c = 0; c < NCLS; c++) ssum += expf(v[c] - m);
        float l = m + logf(ssum);
        #pragma unroll
        for (int c = 0; c < NCLS; c++) out[(size_t)n * NCLS + c] = v[c] - l;
    }
}

// ---------------- launch -----------------------------------------------------
extern "C" void kernel_launch(void* const* d_in, const int* in_sizes, int n_in,
                              void* d_out, int out_size)
{
    const float* x     = (const float*)d_in[0];
    const void*  ei    = d_in[1];
    const float* Wl1   = (const float*)d_in[2];
    const float* bl1   = (const float*)d_in[3];
    const float* Wr1   = (const float*)d_in[4];
    const float* br1   = (const float*)d_in[5];
    const float* att1  = (const float*)d_in[6];
    const float* bias1 = (const float*)d_in[7];
    const float* Wl2   = (const float*)d_in[8];
    const float* bl2   = (const float*)d_in[9];
    const float* Wr2   = (const float*)d_in[10];
    const float* br2   = (const float*)d_in[11];
    const float* att2  = (const float*)d_in[12];
    const float* bias2 = (const float*)d_in[13];

    const int E  = in_sizes[1] / 2;          // 1,600,000
    const int E2 = E + N_NODES;

    // one-time resource setup (first call = eager correctness run, not capture)
    static cudaStream_t s_side = nullptr;
    static cudaEvent_t  ev_fork = nullptr, ev_join = nullptr;
    static void* deg_addr = nullptr;
    if (s_side == nullptr) {
        cudaStreamCreateWithFlags(&s_side, cudaStreamNonBlocking);
        cudaEventCreateWithFlags(&ev_fork, cudaEventDisableTiming);
        cudaEventCreateWithFlags(&ev_join, cudaEventDisableTiming);
        cudaGetSymbolAddress(&deg_addr, g_deg);
        cudaFuncSetAttribute(proj1_kernel,
                             cudaFuncAttributeMaxDynamicSharedMemorySize, PROJ_SMEM);
    }

    const int nodeWarpBlocks = (N_NODES + 7) / 8;

    // fork: projection chain on side stream
    cudaEventRecord(ev_fork, 0);
    cudaStreamWaitEvent(s_side, ev_fork, 0);
    prepB_kernel<<<(128 * FEAT + 255) / 256, 256, 0, s_side>>>(Wl1, Wr1);
    proj1_kernel<<<(N_NODES + 63) / 64, 128, PROJ_SMEM, s_side>>>(x, bl1, br1);
    cudaEventRecord(ev_join, s_side);

    // adjacency chain on main (capture-origin) stream: one-pass bucket scatter
    cudaMemsetAsync(deg_addr, 0, N_NODES * sizeof(int), 0);
    probe_kernel<<<1, 1>>>((const int*)ei);
    scatter_kernel<<<(E2 + 255) / 256, 256>>>(ei, E);

    // join: aggregation needs both chains
    cudaStreamWaitEvent(0, ev_join, 0);
    agg1_kernel<<<nodeWarpBlocks, 256>>>(att1, bias1, Wl2, bl2, Wr2, br2);
    agg2_kernel<<<nodeWarpBlocks, 256>>>(att2, bias2, (float*)d_out);
}